// round 15
// baseline (speedup 1.0000x reference)
#include <cuda_runtime.h>
#include <cuda_fp16.h>
#include <math.h>
#include <stdint.h>

// Problem constants (B=2, S=2048 -> N=4096 tokens)
#define NTOK 4096
#define DDIM 1024
#define IDIM 2048
#define NEXP 8
#define TOPK 2
#define BM   128
#define MAXROWS 9216
#define NTILES  72
#define NSHARED_TILES (NTOK / BM)   // 32
#define GROWS (MAXROWS + NTOK)

// ---------------- scratch (device globals) ----------------
__device__ __align__(16) __half g_W1[(size_t)9 * DDIM * IDIM];
__device__ __align__(16) __half g_W2[(size_t)9 * DDIM * IDIM];
__device__ __align__(16) __half g_Wd[(size_t)9 * IDIM * DDIM];
__device__ __align__(16) __half g_X[(size_t)NTOK * DDIM];
__device__ __align__(16) __half g_Gf[(size_t)GROWS * IDIM];

__device__ int   g_topk_idx[NTOK * TOPK];
__device__ float g_topk_w[NTOK * TOPK];
__device__ float g_probs[NTOK * NEXP];
__device__ int   g_cursor[NEXP];
__device__ int   g_off[NEXP + 1];
__device__ int   g_pair_token[MAXROWS];
__device__ float g_pair_w[MAXROWS];
__device__ int   g_tile_expert[NTILES];

// ---------------- helpers ----------------
__device__ __forceinline__ uint32_t smem_u32(const void* p) {
    uint32_t a;
    asm("{ .reg .u64 t; cvta.to.shared.u64 t, %1; cvt.u32.u64 %0, t; }" : "=r"(a) : "l"(p));
    return a;
}
__device__ __forceinline__ void ldsm_x4(uint32_t* r, uint32_t addr) {
    asm volatile("ldmatrix.sync.aligned.m8n8.x4.shared.b16 {%0,%1,%2,%3}, [%4];"
                 : "=r"(r[0]), "=r"(r[1]), "=r"(r[2]), "=r"(r[3]) : "r"(addr));
}
__device__ __forceinline__ void ldsm_x4_t(uint32_t* r, uint32_t addr) {
    asm volatile("ldmatrix.sync.aligned.m8n8.x4.trans.shared.b16 {%0,%1,%2,%3}, [%4];"
                 : "=r"(r[0]), "=r"(r[1]), "=r"(r[2]), "=r"(r[3]) : "r"(addr));
}
__device__ __forceinline__ void mma16816(float* c, const uint32_t* a, const uint32_t* b) {
    asm volatile("mma.sync.aligned.m16n8k16.row.col.f32.f16.f16.f32 "
                 "{%0,%1,%2,%3}, {%4,%5,%6,%7}, {%8,%9}, {%0,%1,%2,%3};"
                 : "+f"(c[0]), "+f"(c[1]), "+f"(c[2]), "+f"(c[3])
                 : "r"(a[0]), "r"(a[1]), "r"(a[2]), "r"(a[3]), "r"(b[0]), "r"(b[1]));
}
__device__ __forceinline__ void cpa16(uint32_t dst, const void* src, uint32_t srcsz) {
    asm volatile("cp.async.cg.shared.global [%0], [%1], 16, %2;"
                 :: "r"(dst), "l"(src), "r"(srcsz) : "memory");
}
#define CP_COMMIT() asm volatile("cp.async.commit_group;" ::: "memory")
#define CP_WAIT(n)  asm volatile("cp.async.wait_group %0;" :: "n"(n) : "memory")
__device__ __forceinline__ void red_add_v4(float* p, float a, float b, float c, float d) {
    asm volatile("red.global.add.v4.f32 [%0], {%1,%2,%3,%4};"
                 :: "l"(p), "f"(a), "f"(b), "f"(c), "f"(d) : "memory");
}

// ---------------- prep: routing + init + fp32->fp16 convert, one launch -------
#define RX_F4 ((long)NTOK * DDIM / 4)
#define RW_F4 ((long)NEXP * DDIM * IDIM / 4)
#define RS_F4 ((long)DDIM * IDIM / 4)
#define CVT_TOTAL_F4 (RX_F4 + 3 * (RW_F4 + RS_F4))
#define NB_ROUTE 512
#define NB_INIT  ((MAXROWS + 255) / 256)
#define NB_CVT   ((int)((CVT_TOTAL_F4 + 255) / 256))
#define NB_PREP  (NB_ROUTE + NB_INIT + NB_CVT)

__global__ void prep_kernel(const float* __restrict__ x, const float* __restrict__ Wg,
                            const float* __restrict__ W_gate, const float* __restrict__ Ws_gate,
                            const float* __restrict__ W_up,   const float* __restrict__ Ws_up,
                            const float* __restrict__ W_down, const float* __restrict__ Ws_down) {
    int bid = blockIdx.x;
    if (bid < NB_ROUTE) {
        int gwarp = (bid * 256 + threadIdx.x) >> 5;
        int lane = threadIdx.x & 31;
        const float* xr = x + (size_t)gwarp * DDIM;
        float acc[NEXP];
#pragma unroll
        for (int e = 0; e < NEXP; e++) acc[e] = 0.f;
        for (int j = lane; j < DDIM; j += 32) {
            float xv = xr[j];
            const float* wr = Wg + (size_t)j * NEXP;
#pragma unroll
            for (int e = 0; e < NEXP; e++) acc[e] = fmaf(xv, wr[e], acc[e]);
        }
#pragma unroll
        for (int e = 0; e < NEXP; e++) {
#pragma unroll
            for (int o = 16; o; o >>= 1) acc[e] += __shfl_xor_sync(0xffffffffu, acc[e], o);
        }
        float mx = acc[0];
#pragma unroll
        for (int e = 1; e < NEXP; e++) mx = fmaxf(mx, acc[e]);
        float p[NEXP], s = 0.f;
#pragma unroll
        for (int e = 0; e < NEXP; e++) { p[e] = expf(acc[e] - mx); s += p[e]; }
        float invs = 1.f / s;
#pragma unroll
        for (int e = 0; e < NEXP; e++) p[e] *= invs;
        if (lane < NEXP) g_probs[gwarp * NEXP + lane] = p[lane];
        if (lane == 0) {
            int i0 = 0;
#pragma unroll
            for (int e = 1; e < NEXP; e++) if (p[e] > p[i0]) i0 = e;
            int i1 = (i0 == 0) ? 1 : 0;
#pragma unroll
            for (int e = 0; e < NEXP; e++) if (e != i0 && p[e] > p[i1]) i1 = e;
            float w0 = p[i0], w1 = p[i1];
            float inv = 1.f / (w0 + w1 + 1e-9f);
            g_topk_idx[gwarp * 2 + 0] = i0;
            g_topk_idx[gwarp * 2 + 1] = i1;
            g_topk_w[gwarp * 2 + 0] = w0 * inv;
            g_topk_w[gwarp * 2 + 1] = w1 * inv;
        }
        return;
    }
    bid -= NB_ROUTE;
    if (bid < NB_INIT) {
        int i = bid * 256 + threadIdx.x;
        if (i < NEXP) g_cursor[i] = 0;
        if (i < MAXROWS) { g_pair_token[i] = -1; g_pair_w[i] = 0.f; }
        return;
    }
    bid -= NB_INIT;
    long i = (long)bid * 256 + threadIdx.x;
    const long SHOe = (long)NEXP * DDIM * IDIM;
    const float* src; __half* dst; long o;
    if (i < RX_F4)                  { src = x;       dst = g_X;         o = i; }
    else if ((i -= RX_F4) < RW_F4)  { src = W_gate;  dst = g_W1;        o = i; }
    else if ((i -= RW_F4) < RS_F4)  { src = Ws_gate; dst = g_W1 + SHOe; o = i; }
    else if ((i -= RS_F4) < RW_F4)  { src = W_up;    dst = g_W2;        o = i; }
    else if ((i -= RW_F4) < RS_F4)  { src = Ws_up;   dst = g_W2 + SHOe; o = i; }
    else if ((i -= RS_F4) < RW_F4)  { src = W_down;  dst = g_Wd;        o = i; }
    else if ((i -= RW_F4) < RS_F4)  { src = Ws_down; dst = g_Wd + SHOe; o = i; }
    else return;
    float4 v = ((const float4*)src)[o];
    __half2 h0 = __floats2half2_rn(v.x, v.y);
    __half2 h1 = __floats2half2_rn(v.z, v.w);
    uint2 w;
    w.x = *reinterpret_cast<uint32_t*>(&h0);
    w.y = *reinterpret_cast<uint32_t*>(&h1);
    ((uint2*)dst)[o] = w;
}

// ---------------- offsets + scatter ----------------
__global__ void offsets_kernel(float* __restrict__ out, int out_size) {
    __shared__ int scnt[NEXP];
    __shared__ float sP[NEXP];
    __shared__ int soff[NEXP + 1];
    int tid = threadIdx.x;
    if (tid < NEXP) { scnt[tid] = 0; sP[tid] = 0.f; }
    __syncthreads();
    for (int i = tid; i < NTOK * TOPK; i += 256)
        atomicAdd(&scnt[g_topk_idx[i]], 1);
    {
        float ps[NEXP];
#pragma unroll
        for (int e = 0; e < NEXP; e++) ps[e] = 0.f;
        for (int i = tid; i < NTOK; i += 256) {
            const float* pr = g_probs + i * NEXP;
#pragma unroll
            for (int e = 0; e < NEXP; e++) ps[e] += pr[e];
        }
#pragma unroll
        for (int e = 0; e < NEXP; e++) atomicAdd(&sP[e], ps[e]);
    }
    __syncthreads();
    if (tid == 0) {
        int acc = 0;
        soff[0] = 0;
        for (int e = 0; e < NEXP; e++) {
            acc += ((scnt[e] + BM - 1) / BM) * BM;
            soff[e + 1] = acc;
        }
#pragma unroll
        for (int e = 0; e <= NEXP; e++) g_off[e] = soff[e];
    }
    __syncthreads();
    if (tid < NTILES) {
        int r = tid * BM, te = 0;
#pragma unroll
        for (int e = 0; e < NEXP; e++)
            if (r >= soff[e] && r < soff[e + 1]) te = e;
        g_tile_expert[tid] = te;
    }
    if (tid < 32) {
        float term = 0.f;
        if (tid < NEXP) {
            float f = (float)scnt[tid] / ((float)(NTOK * TOPK) + 1e-9f);
            float P = sP[tid] / (float)NTOK;
            term = f * P;
        }
#pragma unroll
        for (int o = 16; o; o >>= 1) term += __shfl_xor_sync(0xffffffffu, term, o);
        if (tid == 0) out[out_size - 1] = 0.01f * (float)NEXP * term;
    }
}

__global__ void scatter_kernel() {
    int n = blockIdx.x * blockDim.x + threadIdx.x;
    if (n >= NTOK) return;
#pragma unroll
    for (int k = 0; k < TOPK; k++) {
        int e = g_topk_idx[n * 2 + k];
        int slot = g_off[e] + atomicAdd(&g_cursor[e], 1);
        g_pair_token[slot] = n;
        g_pair_w[slot] = g_topk_w[n * 2 + k];
    }
}

// ---------------- SMEM layout (fp16, BK=64, 3-stage pipeline) ----------------
#define STAGES 3
#define BK 64
#define A_STRIDE 144                        // 64 fp16 = 128B data + 16B pad
#define A_BYTES  (128 * A_STRIDE)           // 18432
#define UG_BSTRIDE 144
#define UG_BBYTES  (BK * UG_BSTRIDE)        // 9216 per matrix
#define UG_A  0
#define UG_BG A_BYTES
#define UG_BU (UG_BG + UG_BBYTES)
#define UG_STAGE (UG_BU + UG_BBYTES)        // 36864
#define UG_SMEM (STAGES * UG_STAGE)         // 110592 (2 CTAs/SM: 221KB <= 228KB)

#define DN_BSTRIDE 272
#define DN_BBYTES  (BK * DN_BSTRIDE)        // 17408
#define DN_A  0
#define DN_B  A_BYTES
#define DN_STAGE (DN_B + DN_BBYTES)         // 35840
#define DN_SMEM (STAGES * DN_STAGE)         // 107520 (>= 64KB C-stage)

// ---------------- up/gate GEMM + SiLU: 256 thr, 8 warps, warp tile 32x64 ------
__global__ void __launch_bounds__(256, 2)
upgate_all() {
    extern __shared__ char smem[];
    uint32_t sb = smem_u32(smem);
    int tid = threadIdx.x;
    int wid = tid >> 5, lane = tid & 31;
    int by = blockIdx.y, n0 = blockIdx.x * 64;

    bool routed = (by >= NSHARED_TILES);
    int m0, gbase, e;
    if (!routed) { m0 = by * BM; gbase = MAXROWS + m0; e = NEXP; }
    else {
        int t = by - NSHARED_TILES;
        m0 = t * BM;
        if (m0 >= g_off[NEXP]) return;
        gbase = m0;
        e = g_tile_expert[t];
    }

    const __half* w1 = g_W1 + (size_t)e * DDIM * IDIM;
    const __half* w2 = g_W2 + (size_t)e * DDIM * IDIM;

    // A loader: row = tid>>1 (0..127), 4 chunks of 16B at chunk idx (tid&1)*4 + j
    int arow = tid >> 1, acb = (tid & 1) * 4;
    int atok = routed ? g_pair_token[m0 + arow] : (m0 + arow);
    uint32_t asz = (atok >= 0) ? 16u : 0u;
    const __half* asrc = g_X + (size_t)(atok >= 0 ? atok : 0) * DDIM + acb * 8;
    uint32_t dA = (uint32_t)(arow * A_STRIDE + acb * 16);
    // B loader: row = tid>>2 (0..63), chunks (tid&3) and (tid&3)+4 per matrix
    int brow = tid >> 2, bc = (tid & 3) * 8;
    uint32_t dB = (uint32_t)(brow * UG_BSTRIDE + bc * 2);
    size_t bsrc = (size_t)brow * IDIM + n0 + bc;

    const int NST = DDIM / BK;  // 16

#define UG_ISSUE(s_) do { \
        uint32_t st = sb + (uint32_t)(((s_) % STAGES) * UG_STAGE); \
        int k0 = (s_) * BK; \
        cpa16(st + UG_A + dA,      asrc + k0,      asz); \
        cpa16(st + UG_A + dA + 16, asrc + k0 + 8,  asz); \
        cpa16(st + UG_A + dA + 32, asrc + k0 + 16, asz); \
        cpa16(st + UG_A + dA + 48, asrc + k0 + 24, asz); \
        size_t bo = bsrc + (size_t)k0 * IDIM; \
        cpa16(st + UG_BG + dB,      w1 + bo,      16u); \
        cpa16(st + UG_BG + dB + 64, w1 + bo + 32, 16u); \
        cpa16(st + UG_BU + dB,      w2 + bo,      16u); \
        cpa16(st + UG_BU + dB + 64, w2 + bo + 32, 16u); \
    } while (0)

    UG_ISSUE(0); CP_COMMIT();
    UG_ISSUE(1); CP_COMMIT();

    int arow_l = (lane & 7) + ((lane >> 3) & 1) * 8;
    int akc_l = (lane >> 4) * 8;
    int mw = (wid & 3) * 32;
    bool isGate = (wid < 4);
    uint32_t bBase = isGate ? UG_BG : UG_BU;

    float acc[2][8][4];
#pragma unroll
    for (int i = 0; i < 2; i++)
#pragma unroll
        for (int j = 0; j < 8; j++)
#pragma unroll
            for (int q = 0; q < 4; q++) acc[i][j][q] = 0.f;

    for (int s = 0; s < NST; s++) {
        CP_WAIT(1);
        __syncthreads();
        if (s + 2 < NST) UG_ISSUE(s + 2);
        CP_COMMIT();
        uint32_t stg = sb + (uint32_t)((s % STAGES) * UG_STAGE);
#pragma unroll
        for (int ks = 0; ks < BK; ks += 16) {
            uint32_t aF[2][4];
#pragma unroll
            for (int mt = 0; mt < 2; mt++) {
                uint32_t ao = (mw + mt * 16 + arow_l) * A_STRIDE + (ks + akc_l) * 2;
                ldsm_x4(aF[mt], stg + UG_A + ao);
            }
#pragma unroll
            for (int g = 0; g < 4; g++) {
                uint32_t bo = (ks + arow_l) * UG_BSTRIDE + (g * 16 + akc_l) * 2;
                uint32_t bF[4];
                ldsm_x4_t(bF, stg + bBase + bo);
#pragma unroll
                for (int mt = 0; mt < 2; mt++)
#pragma unroll
                    for (int sub = 0; sub < 2; sub++)
                        mma16816(acc[mt][g * 2 + sub], aF[mt], bF + sub * 2);
            }
        }
        __syncthreads();
    }
    CP_WAIT(0);
    __syncthreads();

    // epilogue: exchange up through smem, apply SiLU, write G fp16
    float* exch = (float*)smem;  // 128x64 fp32 = 32KB
    int fr = lane >> 2, fc = (lane & 3) * 2;
    if (!isGate) {
#pragma unroll
        for (int mt = 0; mt < 2; mt++)
#pragma unroll
            for (int j = 0; j < 8; j++) {
                float* c = acc[mt][j];
                int r = mw + mt * 16 + fr, cl = j * 8 + fc;
                *(float2*)&exch[r * 64 + cl] = make_float2(c[0], c[1]);
                *(float2*)&exch[(r + 8) * 64 + cl] = make_float2(c[2], c[3]);
            }
    }
    __syncthreads();
    if (isGate) {
#pragma unroll
        for (int mt = 0; mt < 2; mt++)
#pragma unroll
            for (int j = 0; j < 8; j++) {
                float* c = acc[mt][j];
                int r = mw + mt * 16 + fr, cl = j * 8 + fc;
                float2 u0 = *(float2*)&exch[r * 64 + cl];
                float2 u1 = *(float2*)&exch[(r + 8) * 64 + cl];
                float2 g0, g1;
                g0.x = c[0] / (1.f + __expf(-c[0])) * u0.x;
                g0.y = c[1] / (1.f + __expf(-c[1])) * u0.y;
                g1.x = c[2] / (1.f + __expf(-c[2])) * u1.x;
                g1.y = c[3] / (1.f + __expf(-c[3])) * u1.y;
                *(float2*)&exch[r * 64 + cl] = g0;
                *(float2*)&exch[(r + 8) * 64 + cl] = g1;
            }
    }
    __syncthreads();
    {
        int r = tid >> 1, cb = (tid & 1) * 32;
        const float4* src = (const float4*)&exch[r * 64 + cb];
        __half* dst = g_Gf + (size_t)(gbase + r) * IDIM + n0 + cb;
#pragma unroll
        for (int j = 0; j < 8; j++) {
            float4 v = src[j];
            __half2 h0 = __floats2half2_rn(v.x, v.y);
            __half2 h1 = __floats2half2_rn(v.z, v.w);
            uint2 o;
            o.x = *reinterpret_cast<uint32_t*>(&h0);
            o.y = *reinterpret_cast<uint32_t*>(&h1);
            ((uint2*)dst)[j] = o;
        }
    }
#undef UG_ISSUE
}

// ---------------- down GEMM: 256 thr, 8 warps (4x2), warp tile 32x64 ----------
__global__ void __launch_bounds__(256, 2)
down_all(float* __restrict__ out) {
    extern __shared__ char smem[];
    uint32_t sb = smem_u32(smem);
    int tid = threadIdx.x;
    int wid = tid >> 5, lane = tid & 31;
    int by = blockIdx.y, n0 = blockIdx.x * 128;

    bool routed = (by >= NSHARED_TILES);
    int m0, gbase, e;
    if (!routed) { m0 = by * BM; gbase = MAXROWS + m0; e = NEXP; }
    else {
        int t = by - NSHARED_TILES;
        m0 = t * BM;
        if (m0 >= g_off[NEXP]) return;
        gbase = m0;
        e = g_tile_expert[t];
    }

    const __half* w = g_Wd + (size_t)e * IDIM * DDIM;

    // A loader: row = tid>>1, 4 chunks at chunk idx (tid&1)*4 + j
    int arow = tid >> 1, acb = (tid & 1) * 4;
    const __half* asrc = g_Gf + (size_t)(gbase + arow) * IDIM + acb * 8;
    uint32_t dA = (uint32_t)(arow * A_STRIDE + acb * 16);
    // B loader: row = tid>>2 (0..63), 4 chunks at cols (tid&3)*8 + j*32
    int brow = tid >> 2, bc = (tid & 3) * 8;
    uint32_t dB = (uint32_t)(brow * DN_BSTRIDE + bc * 2);
    size_t bsrc = (size_t)brow * DDIM + n0 + bc;

    const int NST = IDIM / BK;  // 32

#define DN_ISSUE(s_) do { \
        uint32_t st = sb + (uint32_t)(((s_) % STAGES) * DN_STAGE); \
        int k0 = (s_) * BK; \
        cpa16(st + DN_A + dA,      asrc + k0,      16u); \
        cpa16(st + DN_A + dA + 16, asrc + k0 + 8,  16u); \
        cpa16(st + DN_A + dA + 32, asrc + k0 + 16, 16u); \
        cpa16(st + DN_A + dA + 48, asrc + k0 + 24, 16u); \
        size_t bo = bsrc + (size_t)k0 * DDIM; \
        cpa16(st + DN_B + dB,       w + bo,      16u); \
        cpa16(st + DN_B + dB + 64,  w + bo + 32, 16u); \
        cpa16(st + DN_B + dB + 128, w + bo + 64, 16u); \
        cpa16(st + DN_B + dB + 192, w + bo + 96, 16u); \
    } while (0)

    DN_ISSUE(0); CP_COMMIT();
    DN_ISSUE(1); CP_COMMIT();

    int arow_l = (lane & 7) + ((lane >> 3) & 1) * 8;
    int akc_l = (lane >> 4) * 8;
    int mw = (wid >> 1) * 32;
    int nwo = (wid & 1) * 64;

    float acc[2][8][4];
#pragma unroll
    for (int i = 0; i < 2; i++)
#pragma unroll
        for (int j = 0; j < 8; j++)
#pragma unroll
            for (int q = 0; q < 4; q++) acc[i][j][q] = 0.f;

    for (int s = 0; s < NST; s++) {
        CP_WAIT(1);
        __syncthreads();
        if (s + 2 < NST) DN_ISSUE(s + 2);
        CP_COMMIT();
        uint32_t stg = sb + (uint32_t)((s % STAGES) * DN_STAGE);
#pragma unroll
        for (int ks = 0; ks < BK; ks += 16) {
            uint32_t aF[2][4];
#pragma unroll
            for (int mt = 0; mt < 2; mt++) {
                uint32_t ao = (mw + mt * 16 + arow_l) * A_STRIDE + (ks + akc_l) * 2;
                ldsm_x4(aF[mt], stg + DN_A + ao);
            }
#pragma unroll
            for (int g = 0; g < 4; g++) {
                uint32_t bo = (ks + arow_l) * DN_BSTRIDE + (nwo + g * 16 + akc_l) * 2;
                uint32_t bF[4];
                ldsm_x4_t(bF, stg + DN_B + bo);
#pragma unroll
                for (int mt = 0; mt < 2; mt++)
#pragma unroll
                    for (int sub = 0; sub < 2; sub++)
                        mma16816(acc[mt][g * 2 + sub], aF[mt], bF + sub * 2);
            }
        }
        __syncthreads();
    }
    CP_WAIT(0);
    __syncthreads();

    // stage C (128x128 fp32) in smem, then red.add into zeroed out
    float* Cs = (float*)smem;
    int fr = lane >> 2, fc = (lane & 3) * 2;
#pragma unroll
    for (int mt = 0; mt < 2; mt++)
#pragma unroll
        for (int j = 0; j < 8; j++) {
            float* c = acc[mt][j];
            int r = mw + mt * 16 + fr, cl = nwo + j * 8 + fc;
            *(float2*)&Cs[r * 128 + cl] = make_float2(c[0], c[1]);
            *(float2*)&Cs[(r + 8) * 128 + cl] = make_float2(c[2], c[3]);
        }
    __syncthreads();

    int r = tid >> 1, cb = (tid & 1) * 64;
    int tokr = routed ? g_pair_token[m0 + r] : (m0 + r);
    if (tokr >= 0) {
        float wgt = routed ? g_pair_w[m0 + r] : 1.f;
        float* dst = out + (size_t)tokr * DDIM + n0 + cb;
        const float* src = &Cs[r * 128 + cb];
#pragma unroll
        for (int j = 0; j < 16; j++)
            red_add_v4(dst + j * 4, wgt * src[j * 4 + 0], wgt * src[j * 4 + 1],
                       wgt * src[j * 4 + 2], wgt * src[j * 4 + 3]);
    }
#undef DN_ISSUE
}

// ---------------- launch ----------------
extern "C" void kernel_launch(void* const* d_in, const int* in_sizes, int n_in,
                              void* d_out, int out_size) {
    const float* x       = (const float*)d_in[0];
    const float* Wg      = (const float*)d_in[1];
    const float* W_gate  = (const float*)d_in[2];
    const float* W_up    = (const float*)d_in[3];
    const float* W_down  = (const float*)d_in[4];
    const float* Ws_gate = (const float*)d_in[5];
    const float* Ws_up   = (const float*)d_in[6];
    const float* Ws_down = (const float*)d_in[7];
    float* out = (float*)d_out;

    cudaFuncSetAttribute(upgate_all, cudaFuncAttributeMaxDynamicSharedMemorySize, UG_SMEM);
    cudaFuncSetAttribute(down_all,   cudaFuncAttributeMaxDynamicSharedMemorySize, DN_SMEM);

    cudaMemsetAsync(out, 0, (size_t)out_size * sizeof(float));

    prep_kernel<<<NB_PREP, 256>>>(x, Wg, W_gate, Ws_gate, W_up, Ws_up, W_down, Ws_down);
    offsets_kernel<<<1, 256>>>(out, out_size);
    scatter_kernel<<<(NTOK + 255) / 256, 256>>>();

    upgate_all<<<dim3(IDIM / 64, NSHARED_TILES + NTILES), 256, UG_SMEM>>>();
    down_all<<<dim3(DDIM / 128, NSHARED_TILES + NTILES), 256, DN_SMEM>>>(out);
}

// round 16
// speedup vs baseline: 1.0010x; 1.0010x over previous
#include <cuda_runtime.h>
#include <cuda_fp16.h>
#include <math.h>
#include <stdint.h>

// Problem constants (B=2, S=2048 -> N=4096 tokens)
#define NTOK 4096
#define DDIM 1024
#define IDIM 2048
#define NEXP 8
#define TOPK 2
#define BM   128
#define MAXROWS 9216
#define NTILES  72
#define NSHARED_TILES (NTOK / BM)   // 32
#define GROWS (MAXROWS + NTOK)

// ---------------- scratch (device globals) ----------------
__device__ __align__(16) __half g_W1[(size_t)9 * DDIM * IDIM];
__device__ __align__(16) __half g_W2[(size_t)9 * DDIM * IDIM];
__device__ __align__(16) __half g_Wd[(size_t)9 * IDIM * DDIM];
__device__ __align__(16) __half g_X[(size_t)NTOK * DDIM];
__device__ __align__(16) __half g_Gf[(size_t)GROWS * IDIM];

__device__ int   g_topk_idx[NTOK * TOPK];
__device__ float g_topk_w[NTOK * TOPK];
__device__ float g_probs[NTOK * NEXP];
__device__ int   g_cursor[NEXP];
__device__ int   g_off[NEXP + 1];
__device__ int   g_pair_token[MAXROWS];
__device__ float g_pair_w[MAXROWS];
__device__ int   g_tile_expert[NTILES];

// ---------------- helpers ----------------
__device__ __forceinline__ uint32_t smem_u32(const void* p) {
    uint32_t a;
    asm("{ .reg .u64 t; cvta.to.shared.u64 t, %1; cvt.u32.u64 %0, t; }" : "=r"(a) : "l"(p));
    return a;
}
__device__ __forceinline__ void ldsm_x4(uint32_t* r, uint32_t addr) {
    asm volatile("ldmatrix.sync.aligned.m8n8.x4.shared.b16 {%0,%1,%2,%3}, [%4];"
                 : "=r"(r[0]), "=r"(r[1]), "=r"(r[2]), "=r"(r[3]) : "r"(addr));
}
__device__ __forceinline__ void ldsm_x4_t(uint32_t* r, uint32_t addr) {
    asm volatile("ldmatrix.sync.aligned.m8n8.x4.trans.shared.b16 {%0,%1,%2,%3}, [%4];"
                 : "=r"(r[0]), "=r"(r[1]), "=r"(r[2]), "=r"(r[3]) : "r"(addr));
}
__device__ __forceinline__ void mma16816(float* c, const uint32_t* a, const uint32_t* b) {
    asm volatile("mma.sync.aligned.m16n8k16.row.col.f32.f16.f16.f32 "
                 "{%0,%1,%2,%3}, {%4,%5,%6,%7}, {%8,%9}, {%0,%1,%2,%3};"
                 : "+f"(c[0]), "+f"(c[1]), "+f"(c[2]), "+f"(c[3])
                 : "r"(a[0]), "r"(a[1]), "r"(a[2]), "r"(a[3]), "r"(b[0]), "r"(b[1]));
}
__device__ __forceinline__ void cpa16(uint32_t dst, const void* src, uint32_t srcsz) {
    asm volatile("cp.async.cg.shared.global [%0], [%1], 16, %2;"
                 :: "r"(dst), "l"(src), "r"(srcsz) : "memory");
}
#define CP_COMMIT() asm volatile("cp.async.commit_group;" ::: "memory")
#define CP_WAIT(n)  asm volatile("cp.async.wait_group %0;" :: "n"(n) : "memory")
__device__ __forceinline__ void red_add_v4(float* p, float a, float b, float c, float d) {
    asm volatile("red.global.add.v4.f32 [%0], {%1,%2,%3,%4};"
                 :: "l"(p), "f"(a), "f"(b), "f"(c), "f"(d) : "memory");
}

// ---------------- prep: routing + init + fp32->fp16 convert, one launch -------
#define RX_F4 ((long)NTOK * DDIM / 4)
#define RW_F4 ((long)NEXP * DDIM * IDIM / 4)
#define RS_F4 ((long)DDIM * IDIM / 4)
#define CVT_TOTAL_F4 (RX_F4 + 3 * (RW_F4 + RS_F4))
#define NB_ROUTE 512
#define NB_INIT  ((MAXROWS + 255) / 256)
#define NB_CVT   ((int)((CVT_TOTAL_F4 + 255) / 256))
#define NB_PREP  (NB_ROUTE + NB_INIT + NB_CVT)

__global__ void prep_kernel(const float* __restrict__ x, const float* __restrict__ Wg,
                            const float* __restrict__ W_gate, const float* __restrict__ Ws_gate,
                            const float* __restrict__ W_up,   const float* __restrict__ Ws_up,
                            const float* __restrict__ W_down, const float* __restrict__ Ws_down) {
    int bid = blockIdx.x;
    if (bid < NB_ROUTE) {
        int gwarp = (bid * 256 + threadIdx.x) >> 5;
        int lane = threadIdx.x & 31;
        const float* xr = x + (size_t)gwarp * DDIM;
        float acc[NEXP];
#pragma unroll
        for (int e = 0; e < NEXP; e++) acc[e] = 0.f;
        for (int j = lane; j < DDIM; j += 32) {
            float xv = xr[j];
            const float* wr = Wg + (size_t)j * NEXP;
#pragma unroll
            for (int e = 0; e < NEXP; e++) acc[e] = fmaf(xv, wr[e], acc[e]);
        }
#pragma unroll
        for (int e = 0; e < NEXP; e++) {
#pragma unroll
            for (int o = 16; o; o >>= 1) acc[e] += __shfl_xor_sync(0xffffffffu, acc[e], o);
        }
        float mx = acc[0];
#pragma unroll
        for (int e = 1; e < NEXP; e++) mx = fmaxf(mx, acc[e]);
        float p[NEXP], s = 0.f;
#pragma unroll
        for (int e = 0; e < NEXP; e++) { p[e] = expf(acc[e] - mx); s += p[e]; }
        float invs = 1.f / s;
#pragma unroll
        for (int e = 0; e < NEXP; e++) p[e] *= invs;
        if (lane < NEXP) g_probs[gwarp * NEXP + lane] = p[lane];
        if (lane == 0) {
            int i0 = 0;
#pragma unroll
            for (int e = 1; e < NEXP; e++) if (p[e] > p[i0]) i0 = e;
            int i1 = (i0 == 0) ? 1 : 0;
#pragma unroll
            for (int e = 0; e < NEXP; e++) if (e != i0 && p[e] > p[i1]) i1 = e;
            float w0 = p[i0], w1 = p[i1];
            float inv = 1.f / (w0 + w1 + 1e-9f);
            g_topk_idx[gwarp * 2 + 0] = i0;
            g_topk_idx[gwarp * 2 + 1] = i1;
            g_topk_w[gwarp * 2 + 0] = w0 * inv;
            g_topk_w[gwarp * 2 + 1] = w1 * inv;
        }
        return;
    }
    bid -= NB_ROUTE;
    if (bid < NB_INIT) {
        int i = bid * 256 + threadIdx.x;
        if (i < NEXP) g_cursor[i] = 0;
        if (i < MAXROWS) { g_pair_token[i] = -1; g_pair_w[i] = 0.f; }
        return;
    }
    bid -= NB_INIT;
    long i = (long)bid * 256 + threadIdx.x;
    const long SHOe = (long)NEXP * DDIM * IDIM;
    const float* src; __half* dst; long o;
    if (i < RX_F4)                  { src = x;       dst = g_X;         o = i; }
    else if ((i -= RX_F4) < RW_F4)  { src = W_gate;  dst = g_W1;        o = i; }
    else if ((i -= RW_F4) < RS_F4)  { src = Ws_gate; dst = g_W1 + SHOe; o = i; }
    else if ((i -= RS_F4) < RW_F4)  { src = W_up;    dst = g_W2;        o = i; }
    else if ((i -= RW_F4) < RS_F4)  { src = Ws_up;   dst = g_W2 + SHOe; o = i; }
    else if ((i -= RS_F4) < RW_F4)  { src = W_down;  dst = g_Wd;        o = i; }
    else if ((i -= RW_F4) < RS_F4)  { src = Ws_down; dst = g_Wd + SHOe; o = i; }
    else return;
    float4 v = ((const float4*)src)[o];
    __half2 h0 = __floats2half2_rn(v.x, v.y);
    __half2 h1 = __floats2half2_rn(v.z, v.w);
    uint2 w;
    w.x = *reinterpret_cast<uint32_t*>(&h0);
    w.y = *reinterpret_cast<uint32_t*>(&h1);
    ((uint2*)dst)[o] = w;
}

// ---------------- offsets + scatter ----------------
__global__ void offsets_kernel(float* __restrict__ out, int out_size) {
    __shared__ int scnt[NEXP];
    __shared__ float sP[NEXP];
    __shared__ int soff[NEXP + 1];
    int tid = threadIdx.x;
    if (tid < NEXP) { scnt[tid] = 0; sP[tid] = 0.f; }
    __syncthreads();
    for (int i = tid; i < NTOK * TOPK; i += 256)
        atomicAdd(&scnt[g_topk_idx[i]], 1);
    {
        float ps[NEXP];
#pragma unroll
        for (int e = 0; e < NEXP; e++) ps[e] = 0.f;
        for (int i = tid; i < NTOK; i += 256) {
            const float* pr = g_probs + i * NEXP;
#pragma unroll
            for (int e = 0; e < NEXP; e++) ps[e] += pr[e];
        }
#pragma unroll
        for (int e = 0; e < NEXP; e++) atomicAdd(&sP[e], ps[e]);
    }
    __syncthreads();
    if (tid == 0) {
        int acc = 0;
        soff[0] = 0;
        for (int e = 0; e < NEXP; e++) {
            acc += ((scnt[e] + BM - 1) / BM) * BM;
            soff[e + 1] = acc;
        }
#pragma unroll
        for (int e = 0; e <= NEXP; e++) g_off[e] = soff[e];
    }
    __syncthreads();
    if (tid < NTILES) {
        int r = tid * BM, te = 0;
#pragma unroll
        for (int e = 0; e < NEXP; e++)
            if (r >= soff[e] && r < soff[e + 1]) te = e;
        g_tile_expert[tid] = te;
    }
    if (tid < 32) {
        float term = 0.f;
        if (tid < NEXP) {
            float f = (float)scnt[tid] / ((float)(NTOK * TOPK) + 1e-9f);
            float P = sP[tid] / (float)NTOK;
            term = f * P;
        }
#pragma unroll
        for (int o = 16; o; o >>= 1) term += __shfl_xor_sync(0xffffffffu, term, o);
        if (tid == 0) out[out_size - 1] = 0.01f * (float)NEXP * term;
    }
}

__global__ void scatter_kernel() {
    int n = blockIdx.x * blockDim.x + threadIdx.x;
    if (n >= NTOK) return;
#pragma unroll
    for (int k = 0; k < TOPK; k++) {
        int e = g_topk_idx[n * 2 + k];
        int slot = g_off[e] + atomicAdd(&g_cursor[e], 1);
        g_pair_token[slot] = n;
        g_pair_w[slot] = g_topk_w[n * 2 + k];
    }
}

// ---------------- SMEM layout (fp16, BK=64, 3-stage pipeline) ----------------
#define STAGES 3
#define BK 64
#define A_STRIDE 144                        // 64 fp16 = 128B data + 16B pad
#define A_BYTES  (128 * A_STRIDE)           // 18432
#define UG_BSTRIDE 144
#define UG_BBYTES  (BK * UG_BSTRIDE)        // 9216 per matrix
#define UG_A  0
#define UG_BG A_BYTES
#define UG_BU (UG_BG + UG_BBYTES)
#define UG_STAGE (UG_BU + UG_BBYTES)        // 36864
#define UG_SMEM (STAGES * UG_STAGE)         // 110592 (2 CTAs/SM: 221KB <= 228KB)

#define DN_BSTRIDE 272
#define DN_BBYTES  (BK * DN_BSTRIDE)        // 17408
#define DN_A  0
#define DN_B  A_BYTES
#define DN_STAGE (DN_B + DN_BBYTES)         // 35840
#define DN_SMEM (STAGES * DN_STAGE)         // 107520 (>= 64KB C-stage)

// ---------------- up/gate GEMM + SiLU: 256 thr, 8 warps, warp tile 32x64 ------
__global__ void __launch_bounds__(256, 2)
upgate_all() {
    extern __shared__ char smem[];
    uint32_t sb = smem_u32(smem);
    int tid = threadIdx.x;
    int wid = tid >> 5, lane = tid & 31;
    int by = blockIdx.y, n0 = blockIdx.x * 64;

    bool routed = (by >= NSHARED_TILES);
    int m0, gbase, e;
    if (!routed) { m0 = by * BM; gbase = MAXROWS + m0; e = NEXP; }
    else {
        int t = by - NSHARED_TILES;
        m0 = t * BM;
        if (m0 >= g_off[NEXP]) return;
        gbase = m0;
        e = g_tile_expert[t];
    }

    const __half* w1 = g_W1 + (size_t)e * DDIM * IDIM;
    const __half* w2 = g_W2 + (size_t)e * DDIM * IDIM;

    // A loader: row = tid>>1 (0..127), 4 chunks of 16B at chunk idx (tid&1)*4 + j
    int arow = tid >> 1, acb = (tid & 1) * 4;
    int atok = routed ? g_pair_token[m0 + arow] : (m0 + arow);
    uint32_t asz = (atok >= 0) ? 16u : 0u;
    const __half* asrc = g_X + (size_t)(atok >= 0 ? atok : 0) * DDIM + acb * 8;
    uint32_t dA = (uint32_t)(arow * A_STRIDE + acb * 16);
    // B loader: row = tid>>2 (0..63), chunks (tid&3) and (tid&3)+4 per matrix
    int brow = tid >> 2, bc = (tid & 3) * 8;
    uint32_t dB = (uint32_t)(brow * UG_BSTRIDE + bc * 2);
    size_t bsrc = (size_t)brow * IDIM + n0 + bc;

    const int NST = DDIM / BK;  // 16

#define UG_ISSUE(s_) do { \
        uint32_t st = sb + (uint32_t)(((s_) % STAGES) * UG_STAGE); \
        int k0 = (s_) * BK; \
        cpa16(st + UG_A + dA,      asrc + k0,      asz); \
        cpa16(st + UG_A + dA + 16, asrc + k0 + 8,  asz); \
        cpa16(st + UG_A + dA + 32, asrc + k0 + 16, asz); \
        cpa16(st + UG_A + dA + 48, asrc + k0 + 24, asz); \
        size_t bo = bsrc + (size_t)k0 * IDIM; \
        cpa16(st + UG_BG + dB,      w1 + bo,      16u); \
        cpa16(st + UG_BG + dB + 64, w1 + bo + 32, 16u); \
        cpa16(st + UG_BU + dB,      w2 + bo,      16u); \
        cpa16(st + UG_BU + dB + 64, w2 + bo + 32, 16u); \
    } while (0)

    UG_ISSUE(0); CP_COMMIT();
    UG_ISSUE(1); CP_COMMIT();

    int arow_l = (lane & 7) + ((lane >> 3) & 1) * 8;
    int akc_l = (lane >> 4) * 8;
    int mw = (wid & 3) * 32;
    bool isGate = (wid < 4);
    uint32_t bBase = isGate ? UG_BG : UG_BU;

    float acc[2][8][4];
#pragma unroll
    for (int i = 0; i < 2; i++)
#pragma unroll
        for (int j = 0; j < 8; j++)
#pragma unroll
            for (int q = 0; q < 4; q++) acc[i][j][q] = 0.f;

    for (int s = 0; s < NST; s++) {
        CP_WAIT(1);
        __syncthreads();
        if (s + 2 < NST) UG_ISSUE(s + 2);
        CP_COMMIT();
        uint32_t stg = sb + (uint32_t)((s % STAGES) * UG_STAGE);
#pragma unroll
        for (int ks = 0; ks < BK; ks += 16) {
            uint32_t aF[2][4];
#pragma unroll
            for (int mt = 0; mt < 2; mt++) {
                uint32_t ao = (mw + mt * 16 + arow_l) * A_STRIDE + (ks + akc_l) * 2;
                ldsm_x4(aF[mt], stg + UG_A + ao);
            }
#pragma unroll
            for (int g = 0; g < 4; g++) {
                uint32_t bo = (ks + arow_l) * UG_BSTRIDE + (g * 16 + akc_l) * 2;
                uint32_t bF[4];
                ldsm_x4_t(bF, stg + bBase + bo);
#pragma unroll
                for (int mt = 0; mt < 2; mt++)
#pragma unroll
                    for (int sub = 0; sub < 2; sub++)
                        mma16816(acc[mt][g * 2 + sub], aF[mt], bF + sub * 2);
            }
        }
        __syncthreads();
    }
    CP_WAIT(0);
    __syncthreads();

    // epilogue: exchange up through smem, apply SiLU, write G fp16
    float* exch = (float*)smem;  // 128x64 fp32 = 32KB
    int fr = lane >> 2, fc = (lane & 3) * 2;
    if (!isGate) {
#pragma unroll
        for (int mt = 0; mt < 2; mt++)
#pragma unroll
            for (int j = 0; j < 8; j++) {
                float* c = acc[mt][j];
                int r = mw + mt * 16 + fr, cl = j * 8 + fc;
                *(float2*)&exch[r * 64 + cl] = make_float2(c[0], c[1]);
                *(float2*)&exch[(r + 8) * 64 + cl] = make_float2(c[2], c[3]);
            }
    }
    __syncthreads();
    if (isGate) {
#pragma unroll
        for (int mt = 0; mt < 2; mt++)
#pragma unroll
            for (int j = 0; j < 8; j++) {
                float* c = acc[mt][j];
                int r = mw + mt * 16 + fr, cl = j * 8 + fc;
                float2 u0 = *(float2*)&exch[r * 64 + cl];
                float2 u1 = *(float2*)&exch[(r + 8) * 64 + cl];
                float2 g0, g1;
                g0.x = c[0] / (1.f + __expf(-c[0])) * u0.x;
                g0.y = c[1] / (1.f + __expf(-c[1])) * u0.y;
                g1.x = c[2] / (1.f + __expf(-c[2])) * u1.x;
                g1.y = c[3] / (1.f + __expf(-c[3])) * u1.y;
                *(float2*)&exch[r * 64 + cl] = g0;
                *(float2*)&exch[(r + 8) * 64 + cl] = g1;
            }
    }
    __syncthreads();
    {
        int r = tid >> 1, cb = (tid & 1) * 32;
        const float4* src = (const float4*)&exch[r * 64 + cb];
        __half* dst = g_Gf + (size_t)(gbase + r) * IDIM + n0 + cb;
#pragma unroll
        for (int j = 0; j < 8; j++) {
            float4 v = src[j];
            __half2 h0 = __floats2half2_rn(v.x, v.y);
            __half2 h1 = __floats2half2_rn(v.z, v.w);
            uint2 o;
            o.x = *reinterpret_cast<uint32_t*>(&h0);
            o.y = *reinterpret_cast<uint32_t*>(&h1);
            ((uint2*)dst)[j] = o;
        }
    }
#undef UG_ISSUE
}

// ---------------- down GEMM: 256 thr, 8 warps (4x2), warp tile 32x64 ----------
__global__ void __launch_bounds__(256, 2)
down_all(float* __restrict__ out) {
    extern __shared__ char smem[];
    uint32_t sb = smem_u32(smem);
    int tid = threadIdx.x;
    int wid = tid >> 5, lane = tid & 31;
    int by = blockIdx.y, n0 = blockIdx.x * 128;

    bool routed = (by >= NSHARED_TILES);
    int m0, gbase, e;
    if (!routed) { m0 = by * BM; gbase = MAXROWS + m0; e = NEXP; }
    else {
        int t = by - NSHARED_TILES;
        m0 = t * BM;
        if (m0 >= g_off[NEXP]) return;
        gbase = m0;
        e = g_tile_expert[t];
    }

    const __half* w = g_Wd + (size_t)e * IDIM * DDIM;

    // A loader: row = tid>>1, 4 chunks at chunk idx (tid&1)*4 + j
    int arow = tid >> 1, acb = (tid & 1) * 4;
    const __half* asrc = g_Gf + (size_t)(gbase + arow) * IDIM + acb * 8;
    uint32_t dA = (uint32_t)(arow * A_STRIDE + acb * 16);
    // B loader: row = tid>>2 (0..63), 4 chunks at cols (tid&3)*8 + j*32
    int brow = tid >> 2, bc = (tid & 3) * 8;
    uint32_t dB = (uint32_t)(brow * DN_BSTRIDE + bc * 2);
    size_t bsrc = (size_t)brow * DDIM + n0 + bc;

    const int NST = IDIM / BK;  // 32

#define DN_ISSUE(s_) do { \
        uint32_t st = sb + (uint32_t)(((s_) % STAGES) * DN_STAGE); \
        int k0 = (s_) * BK; \
        cpa16(st + DN_A + dA,      asrc + k0,      16u); \
        cpa16(st + DN_A + dA + 16, asrc + k0 + 8,  16u); \
        cpa16(st + DN_A + dA + 32, asrc + k0 + 16, 16u); \
        cpa16(st + DN_A + dA + 48, asrc + k0 + 24, 16u); \
        size_t bo = bsrc + (size_t)k0 * DDIM; \
        cpa16(st + DN_B + dB,       w + bo,      16u); \
        cpa16(st + DN_B + dB + 64,  w + bo + 32, 16u); \
        cpa16(st + DN_B + dB + 128, w + bo + 64, 16u); \
        cpa16(st + DN_B + dB + 192, w + bo + 96, 16u); \
    } while (0)

    DN_ISSUE(0); CP_COMMIT();
    DN_ISSUE(1); CP_COMMIT();

    int arow_l = (lane & 7) + ((lane >> 3) & 1) * 8;
    int akc_l = (lane >> 4) * 8;
    int mw = (wid >> 1) * 32;
    int nwo = (wid & 1) * 64;

    float acc[2][8][4];
#pragma unroll
    for (int i = 0; i < 2; i++)
#pragma unroll
        for (int j = 0; j < 8; j++)
#pragma unroll
            for (int q = 0; q < 4; q++) acc[i][j][q] = 0.f;

    for (int s = 0; s < NST; s++) {
        CP_WAIT(1);
        __syncthreads();
        if (s + 2 < NST) DN_ISSUE(s + 2);
        CP_COMMIT();
        uint32_t stg = sb + (uint32_t)((s % STAGES) * DN_STAGE);
#pragma unroll
        for (int ks = 0; ks < BK; ks += 16) {
            uint32_t aF[2][4];
#pragma unroll
            for (int mt = 0; mt < 2; mt++) {
                uint32_t ao = (mw + mt * 16 + arow_l) * A_STRIDE + (ks + akc_l) * 2;
                ldsm_x4(aF[mt], stg + DN_A + ao);
            }
#pragma unroll
            for (int g = 0; g < 4; g++) {
                uint32_t bo = (ks + arow_l) * DN_BSTRIDE + (nwo + g * 16 + akc_l) * 2;
                uint32_t bF[4];
                ldsm_x4_t(bF, stg + DN_B + bo);
#pragma unroll
                for (int mt = 0; mt < 2; mt++)
#pragma unroll
                    for (int sub = 0; sub < 2; sub++)
                        mma16816(acc[mt][g * 2 + sub], aF[mt], bF + sub * 2);
            }
        }
        __syncthreads();
    }
    CP_WAIT(0);
    __syncthreads();

    // stage C (128x128 fp32) in smem, then red.add into zeroed out
    float* Cs = (float*)smem;
    int fr = lane >> 2, fc = (lane & 3) * 2;
#pragma unroll
    for (int mt = 0; mt < 2; mt++)
#pragma unroll
        for (int j = 0; j < 8; j++) {
            float* c = acc[mt][j];
            int r = mw + mt * 16 + fr, cl = nwo + j * 8 + fc;
            *(float2*)&Cs[r * 128 + cl] = make_float2(c[0], c[1]);
            *(float2*)&Cs[(r + 8) * 128 + cl] = make_float2(c[2], c[3]);
        }
    __syncthreads();

    int r = tid >> 1, cb = (tid & 1) * 64;
    int tokr = routed ? g_pair_token[m0 + r] : (m0 + r);
    if (tokr >= 0) {
        float wgt = routed ? g_pair_w[m0 + r] : 1.f;
        float* dst = out + (size_t)tokr * DDIM + n0 + cb;
        const float* src = &Cs[r * 128 + cb];
#pragma unroll
        for (int j = 0; j < 16; j++)
            red_add_v4(dst + j * 4, wgt * src[j * 4 + 0], wgt * src[j * 4 + 1],
                       wgt * src[j * 4 + 2], wgt * src[j * 4 + 3]);
    }
#undef DN_ISSUE
}

// ---------------- launch ----------------
extern "C" void kernel_launch(void* const* d_in, const int* in_sizes, int n_in,
                              void* d_out, int out_size) {
    const float* x       = (const float*)d_in[0];
    const float* Wg      = (const float*)d_in[1];
    const float* W_gate  = (const float*)d_in[2];
    const float* W_up    = (const float*)d_in[3];
    const float* W_down  = (const float*)d_in[4];
    const float* Ws_gate = (const float*)d_in[5];
    const float* Ws_up   = (const float*)d_in[6];
    const float* Ws_down = (const float*)d_in[7];
    float* out = (float*)d_out;

    cudaFuncSetAttribute(upgate_all, cudaFuncAttributeMaxDynamicSharedMemorySize, UG_SMEM);
    cudaFuncSetAttribute(down_all,   cudaFuncAttributeMaxDynamicSharedMemorySize, DN_SMEM);

    cudaMemsetAsync(out, 0, (size_t)out_size * sizeof(float));

    prep_kernel<<<NB_PREP, 256>>>(x, Wg, W_gate, Ws_gate, W_up, Ws_up, W_down, Ws_down);
    offsets_kernel<<<1, 256>>>(out, out_size);
    scatter_kernel<<<(NTOK + 255) / 256, 256>>>();

    upgate_all<<<dim3(IDIM / 64, NSHARED_TILES + NTILES), 256, UG_SMEM>>>();
    down_all<<<dim3(DDIM / 128, NSHARED_TILES + NTILES), 256, DN_SMEM>>>(out);
}

// round 17
// speedup vs baseline: 1.3041x; 1.3029x over previous
#include <cuda_runtime.h>
#include <cuda_fp16.h>
#include <math.h>
#include <stdint.h>

// Problem constants (B=2, S=2048 -> N=4096 tokens)
#define NTOK 4096
#define DDIM 1024
#define IDIM 2048
#define NEXP 8
#define TOPK 2
#define BM   128
#define MAXROWS 9216
#define NTILES  72
#define NSHARED_TILES (NTOK / BM)   // 32
#define GROWS (MAXROWS + NTOK)

// ---------------- scratch (device globals) ----------------
__device__ __align__(16) __half g_W1[(size_t)9 * DDIM * IDIM];
__device__ __align__(16) __half g_W2[(size_t)9 * DDIM * IDIM];
__device__ __align__(16) __half g_Wd[(size_t)9 * IDIM * DDIM];
__device__ __align__(16) __half g_X[(size_t)NTOK * DDIM];
__device__ __align__(16) __half g_Gf[(size_t)GROWS * IDIM];

__device__ int   g_topk_idx[NTOK * TOPK];
__device__ float g_topk_w[NTOK * TOPK];
__device__ float g_probs[NTOK * NEXP];
__device__ int   g_cursor[NEXP];
__device__ int   g_off[NEXP + 1];
__device__ int   g_pair_token[MAXROWS];
__device__ float g_pair_w[MAXROWS];
__device__ int   g_tile_expert[NTILES];

// ---------------- helpers ----------------
__device__ __forceinline__ uint32_t smem_u32(const void* p) {
    uint32_t a;
    asm("{ .reg .u64 t; cvta.to.shared.u64 t, %1; cvt.u32.u64 %0, t; }" : "=r"(a) : "l"(p));
    return a;
}
__device__ __forceinline__ void ldsm_x4(uint32_t* r, uint32_t addr) {
    asm volatile("ldmatrix.sync.aligned.m8n8.x4.shared.b16 {%0,%1,%2,%3}, [%4];"
                 : "=r"(r[0]), "=r"(r[1]), "=r"(r[2]), "=r"(r[3]) : "r"(addr));
}
__device__ __forceinline__ void ldsm_x4_t(uint32_t* r, uint32_t addr) {
    asm volatile("ldmatrix.sync.aligned.m8n8.x4.trans.shared.b16 {%0,%1,%2,%3}, [%4];"
                 : "=r"(r[0]), "=r"(r[1]), "=r"(r[2]), "=r"(r[3]) : "r"(addr));
}
__device__ __forceinline__ void mma16816(float* c, const uint32_t* a, const uint32_t* b) {
    asm volatile("mma.sync.aligned.m16n8k16.row.col.f32.f16.f16.f32 "
                 "{%0,%1,%2,%3}, {%4,%5,%6,%7}, {%8,%9}, {%0,%1,%2,%3};"
                 : "+f"(c[0]), "+f"(c[1]), "+f"(c[2]), "+f"(c[3])
                 : "r"(a[0]), "r"(a[1]), "r"(a[2]), "r"(a[3]), "r"(b[0]), "r"(b[1]));
}
__device__ __forceinline__ void cpa16(uint32_t dst, const void* src, uint32_t srcsz) {
    asm volatile("cp.async.cg.shared.global [%0], [%1], 16, %2;"
                 :: "r"(dst), "l"(src), "r"(srcsz) : "memory");
}
#define CP_COMMIT() asm volatile("cp.async.commit_group;" ::: "memory")
#define CP_WAIT(n)  asm volatile("cp.async.wait_group %0;" :: "n"(n) : "memory")
__device__ __forceinline__ void red_add_v4(float* p, float a, float b, float c, float d) {
    asm volatile("red.global.add.v4.f32 [%0], {%1,%2,%3,%4};"
                 :: "l"(p), "f"(a), "f"(b), "f"(c), "f"(d) : "memory");
}

// ---------------- prep: routing + init + fp32->fp16 convert, one launch -------
#define RX_F4 ((long)NTOK * DDIM / 4)
#define RW_F4 ((long)NEXP * DDIM * IDIM / 4)
#define RS_F4 ((long)DDIM * IDIM / 4)
#define CVT_TOTAL_F4 (RX_F4 + 3 * (RW_F4 + RS_F4))
#define NB_ROUTE 512
#define NB_INIT  ((MAXROWS + 255) / 256)
#define NB_CVT   ((int)((CVT_TOTAL_F4 + 255) / 256))
#define NB_PREP  (NB_ROUTE + NB_INIT + NB_CVT)

__global__ void prep_kernel(const float* __restrict__ x, const float* __restrict__ Wg,
                            const float* __restrict__ W_gate, const float* __restrict__ Ws_gate,
                            const float* __restrict__ W_up,   const float* __restrict__ Ws_up,
                            const float* __restrict__ W_down, const float* __restrict__ Ws_down) {
    int bid = blockIdx.x;
    if (bid < NB_ROUTE) {
        int gwarp = (bid * 256 + threadIdx.x) >> 5;
        int lane = threadIdx.x & 31;
        const float* xr = x + (size_t)gwarp * DDIM;
        float acc[NEXP];
#pragma unroll
        for (int e = 0; e < NEXP; e++) acc[e] = 0.f;
        for (int j = lane; j < DDIM; j += 32) {
            float xv = xr[j];
            const float* wr = Wg + (size_t)j * NEXP;
#pragma unroll
            for (int e = 0; e < NEXP; e++) acc[e] = fmaf(xv, wr[e], acc[e]);
        }
#pragma unroll
        for (int e = 0; e < NEXP; e++) {
#pragma unroll
            for (int o = 16; o; o >>= 1) acc[e] += __shfl_xor_sync(0xffffffffu, acc[e], o);
        }
        float mx = acc[0];
#pragma unroll
        for (int e = 1; e < NEXP; e++) mx = fmaxf(mx, acc[e]);
        float p[NEXP], s = 0.f;
#pragma unroll
        for (int e = 0; e < NEXP; e++) { p[e] = expf(acc[e] - mx); s += p[e]; }
        float invs = 1.f / s;
#pragma unroll
        for (int e = 0; e < NEXP; e++) p[e] *= invs;
        if (lane < NEXP) g_probs[gwarp * NEXP + lane] = p[lane];
        if (lane == 0) {
            int i0 = 0;
#pragma unroll
            for (int e = 1; e < NEXP; e++) if (p[e] > p[i0]) i0 = e;
            int i1 = (i0 == 0) ? 1 : 0;
#pragma unroll
            for (int e = 0; e < NEXP; e++) if (e != i0 && p[e] > p[i1]) i1 = e;
            float w0 = p[i0], w1 = p[i1];
            float inv = 1.f / (w0 + w1 + 1e-9f);
            g_topk_idx[gwarp * 2 + 0] = i0;
            g_topk_idx[gwarp * 2 + 1] = i1;
            g_topk_w[gwarp * 2 + 0] = w0 * inv;
            g_topk_w[gwarp * 2 + 1] = w1 * inv;
        }
        return;
    }
    bid -= NB_ROUTE;
    if (bid < NB_INIT) {
        int i = bid * 256 + threadIdx.x;
        if (i < NEXP) g_cursor[i] = 0;
        if (i < MAXROWS) { g_pair_token[i] = -1; g_pair_w[i] = 0.f; }
        return;
    }
    bid -= NB_INIT;
    long i = (long)bid * 256 + threadIdx.x;
    const long SHOe = (long)NEXP * DDIM * IDIM;
    const float* src; __half* dst; long o;
    if (i < RX_F4)                  { src = x;       dst = g_X;         o = i; }
    else if ((i -= RX_F4) < RW_F4)  { src = W_gate;  dst = g_W1;        o = i; }
    else if ((i -= RW_F4) < RS_F4)  { src = Ws_gate; dst = g_W1 + SHOe; o = i; }
    else if ((i -= RS_F4) < RW_F4)  { src = W_up;    dst = g_W2;        o = i; }
    else if ((i -= RW_F4) < RS_F4)  { src = Ws_up;   dst = g_W2 + SHOe; o = i; }
    else if ((i -= RS_F4) < RW_F4)  { src = W_down;  dst = g_Wd;        o = i; }
    else if ((i -= RW_F4) < RS_F4)  { src = Ws_down; dst = g_Wd + SHOe; o = i; }
    else return;
    float4 v = ((const float4*)src)[o];
    __half2 h0 = __floats2half2_rn(v.x, v.y);
    __half2 h1 = __floats2half2_rn(v.z, v.w);
    uint2 w;
    w.x = *reinterpret_cast<uint32_t*>(&h0);
    w.y = *reinterpret_cast<uint32_t*>(&h1);
    ((uint2*)dst)[o] = w;
}

// ---------------- offsets + scatter ----------------
__global__ void offsets_kernel(float* __restrict__ out, int out_size) {
    __shared__ int scnt[NEXP];
    __shared__ float sP[NEXP];
    __shared__ int soff[NEXP + 1];
    int tid = threadIdx.x;
    if (tid < NEXP) { scnt[tid] = 0; sP[tid] = 0.f; }
    __syncthreads();
    for (int i = tid; i < NTOK * TOPK; i += 256)
        atomicAdd(&scnt[g_topk_idx[i]], 1);
    {
        float ps[NEXP];
#pragma unroll
        for (int e = 0; e < NEXP; e++) ps[e] = 0.f;
        for (int i = tid; i < NTOK; i += 256) {
            const float* pr = g_probs + i * NEXP;
#pragma unroll
            for (int e = 0; e < NEXP; e++) ps[e] += pr[e];
        }
#pragma unroll
        for (int e = 0; e < NEXP; e++) atomicAdd(&sP[e], ps[e]);
    }
    __syncthreads();
    if (tid == 0) {
        int acc = 0;
        soff[0] = 0;
        for (int e = 0; e < NEXP; e++) {
            acc += ((scnt[e] + BM - 1) / BM) * BM;
            soff[e + 1] = acc;
        }
#pragma unroll
        for (int e = 0; e <= NEXP; e++) g_off[e] = soff[e];
    }
    __syncthreads();
    if (tid < NTILES) {
        int r = tid * BM, te = 0;
#pragma unroll
        for (int e = 0; e < NEXP; e++)
            if (r >= soff[e] && r < soff[e + 1]) te = e;
        g_tile_expert[tid] = te;
    }
    if (tid < 32) {
        float term = 0.f;
        if (tid < NEXP) {
            float f = (float)scnt[tid] / ((float)(NTOK * TOPK) + 1e-9f);
            float P = sP[tid] / (float)NTOK;
            term = f * P;
        }
#pragma unroll
        for (int o = 16; o; o >>= 1) term += __shfl_xor_sync(0xffffffffu, term, o);
        if (tid == 0) out[out_size - 1] = 0.01f * (float)NEXP * term;
    }
}

__global__ void scatter_kernel() {
    int n = blockIdx.x * blockDim.x + threadIdx.x;
    if (n >= NTOK) return;
#pragma unroll
    for (int k = 0; k < TOPK; k++) {
        int e = g_topk_idx[n * 2 + k];
        int slot = g_off[e] + atomicAdd(&g_cursor[e], 1);
        g_pair_token[slot] = n;
        g_pair_w[slot] = g_topk_w[n * 2 + k];
    }
}

// ---------------- SMEM layout (fp16 tiles, 4-stage pipeline, BK=32) ----------
#define STAGES 4
#define A_STRIDE 80
#define A_BYTES  (128 * A_STRIDE)           // 10240
#define UG_BSTRIDE 144
#define UG_BBYTES  (32 * UG_BSTRIDE)        // 4608
#define UG_A  0
#define UG_BG A_BYTES
#define UG_BU (UG_BG + UG_BBYTES)
#define UG_STAGE (UG_BU + UG_BBYTES)        // 19456
#define UG_SMEM (STAGES * UG_STAGE)         // 77824

#define DN_BSTRIDE 272
#define DN_BBYTES  (32 * DN_BSTRIDE)        // 8704
#define DN_A  0
#define DN_B  A_BYTES
#define DN_STAGE (DN_B + DN_BBYTES)         // 18944
#define DN_SMEM (STAGES * DN_STAGE)         // 75776

// ---------------- up/gate GEMM + SiLU: R8 mainloop, in-register SiLU ----------
// CTA 128M x 64N; 8 warps in 4x2 grid; each warp: gate 32x32 + up 32x32.
__global__ void __launch_bounds__(256, 2)
upgate_all() {
    extern __shared__ char smem[];
    uint32_t sb = smem_u32(smem);
    int tid = threadIdx.x;
    int wid = tid >> 5, lane = tid & 31;
    int by = blockIdx.y, n0 = blockIdx.x * 64;

    bool routed = (by >= NSHARED_TILES);
    int m0, gbase, e;
    if (!routed) { m0 = by * BM; gbase = MAXROWS + m0; e = NEXP; }
    else {
        int t = by - NSHARED_TILES;
        m0 = t * BM;
        if (m0 >= g_off[NEXP]) return;
        gbase = m0;
        e = g_tile_expert[t];
    }

    const __half* w1 = g_W1 + (size_t)e * DDIM * IDIM;
    const __half* w2 = g_W2 + (size_t)e * DDIM * IDIM;

    // A loader: rows r0 and r0+64, one 16B chunk (8 fp16) each
    int r0 = tid >> 2, kq = (tid & 3) * 8;
    int r1 = r0 + 64;
    int t0 = routed ? g_pair_token[m0 + r0] : (m0 + r0);
    int t1 = routed ? g_pair_token[m0 + r1] : (m0 + r1);
    uint32_t sz0 = (t0 >= 0) ? 16u : 0u;
    uint32_t sz1 = (t1 >= 0) ? 16u : 0u;
    const __half* a0 = g_X + (size_t)(t0 >= 0 ? t0 : 0) * DDIM + kq;
    const __half* a1 = g_X + (size_t)(t1 >= 0 ? t1 : 0) * DDIM + kq;
    uint32_t dA0 = UG_A + (uint32_t)(r0 * A_STRIDE + kq * 2);
    uint32_t dA1 = UG_A + (uint32_t)(r1 * A_STRIDE + kq * 2);
    // B loader: row br (0..31), one 16B chunk at col bn per matrix
    int br = tid >> 3, bn = (tid & 7) * 8;
    uint32_t dB = (uint32_t)(br * UG_BSTRIDE + bn * 2);
    size_t bsrc0 = (size_t)br * IDIM + n0 + bn;

    const int NST = DDIM / 32;  // 32

#define UG_ISSUE(s_) do { \
        uint32_t st = sb + (uint32_t)(((s_) % STAGES) * UG_STAGE); \
        int k0 = (s_) * 32; \
        cpa16(st + dA0, a0 + k0, sz0); \
        cpa16(st + dA1, a1 + k0, sz1); \
        size_t bo = bsrc0 + (size_t)k0 * IDIM; \
        cpa16(st + UG_BG + dB, w1 + bo, 16u); \
        cpa16(st + UG_BU + dB, w2 + bo, 16u); \
    } while (0)

    UG_ISSUE(0); CP_COMMIT();
    UG_ISSUE(1); CP_COMMIT();
    UG_ISSUE(2); CP_COMMIT();

    int arow_l = (lane & 7) + ((lane >> 3) & 1) * 8;
    int akc_l = (lane >> 4) * 8;
    int mw = (wid & 3) * 32;        // warp m base (4 m-groups)
    int nw = (wid >> 2) * 32;       // warp n base (2 n-groups)

    float accg[2][4][4], accu[2][4][4];
#pragma unroll
    for (int i = 0; i < 2; i++)
#pragma unroll
        for (int j = 0; j < 4; j++)
#pragma unroll
            for (int q = 0; q < 4; q++) { accg[i][j][q] = 0.f; accu[i][j][q] = 0.f; }

    for (int s = 0; s < NST; s++) {
        CP_WAIT(2);
        __syncthreads();
        if (s + 3 < NST) UG_ISSUE(s + 3);
        CP_COMMIT();
        uint32_t stg = sb + (uint32_t)((s % STAGES) * UG_STAGE);
#pragma unroll
        for (int ks = 0; ks < 32; ks += 16) {
            uint32_t aF[2][4];
#pragma unroll
            for (int mt = 0; mt < 2; mt++) {
                uint32_t ao = (mw + mt * 16 + arow_l) * A_STRIDE + (ks + akc_l) * 2;
                ldsm_x4(aF[mt], stg + UG_A + ao);
            }
#pragma unroll
            for (int g = 0; g < 2; g++) {
                uint32_t bo = (ks + arow_l) * UG_BSTRIDE + (nw + g * 16 + akc_l) * 2;
                uint32_t bG[4], bU[4];
                ldsm_x4_t(bG, stg + UG_BG + bo);
                ldsm_x4_t(bU, stg + UG_BU + bo);
#pragma unroll
                for (int mt = 0; mt < 2; mt++)
#pragma unroll
                    for (int sub = 0; sub < 2; sub++) {
                        mma16816(accg[mt][g * 2 + sub], aF[mt], bG + sub * 2);
                        mma16816(accu[mt][g * 2 + sub], aF[mt], bU + sub * 2);
                    }
            }
        }
    }
    CP_WAIT(0);

    // epilogue: in-register SiLU, store fp16 G directly (no smem exchange)
    int fr = lane >> 2, fc = (lane & 3) * 2;
#pragma unroll
    for (int mt = 0; mt < 2; mt++)
#pragma unroll
        for (int j = 0; j < 4; j++) {
            float* cg = accg[mt][j];
            float* cu = accu[mt][j];
            int r = gbase + mw + mt * 16 + fr;
            int cl = n0 + nw + j * 8 + fc;
            float o0 = cg[0] / (1.f + __expf(-cg[0])) * cu[0];
            float o1 = cg[1] / (1.f + __expf(-cg[1])) * cu[1];
            float o2 = cg[2] / (1.f + __expf(-cg[2])) * cu[2];
            float o3 = cg[3] / (1.f + __expf(-cg[3])) * cu[3];
            __half2 h01 = __floats2half2_rn(o0, o1);
            __half2 h23 = __floats2half2_rn(o2, o3);
            *(uint32_t*)(g_Gf + (size_t)r * IDIM + cl) = *reinterpret_cast<uint32_t*>(&h01);
            *(uint32_t*)(g_Gf + (size_t)(r + 8) * IDIM + cl) = *reinterpret_cast<uint32_t*>(&h23);
        }
#undef UG_ISSUE
}

// ---------------- down GEMM: exact R8 (256 thr, 8 warps 4x2, 32x64 tiles) -----
__global__ void __launch_bounds__(256, 2)
down_all(float* __restrict__ out) {
    extern __shared__ char smem[];
    uint32_t sb = smem_u32(smem);
    int tid = threadIdx.x;
    int wid = tid >> 5, lane = tid & 31;
    int by = blockIdx.y, n0 = blockIdx.x * 128;

    bool routed = (by >= NSHARED_TILES);
    int m0, gbase, e;
    if (!routed) { m0 = by * BM; gbase = MAXROWS + m0; e = NEXP; }
    else {
        int t = by - NSHARED_TILES;
        m0 = t * BM;
        if (m0 >= g_off[NEXP]) return;
        gbase = m0;
        e = g_tile_expert[t];
    }

    const __half* w = g_Wd + (size_t)e * IDIM * DDIM;

    int r0 = tid >> 2, kq = (tid & 3) * 8;
    int r1 = r0 + 64;
    const __half* a0 = g_Gf + (size_t)(gbase + r0) * IDIM + kq;
    const __half* a1 = g_Gf + (size_t)(gbase + r1) * IDIM + kq;
    uint32_t dA0 = DN_A + (uint32_t)(r0 * A_STRIDE + kq * 2);
    uint32_t dA1 = DN_A + (uint32_t)(r1 * A_STRIDE + kq * 2);
    int br0 = tid >> 4, bnc = (tid & 15) * 8;
    int br1 = br0 + 16;
    uint32_t dB0 = (uint32_t)(br0 * DN_BSTRIDE + bnc * 2);
    uint32_t dB1 = (uint32_t)(br1 * DN_BSTRIDE + bnc * 2);
    size_t bs0 = (size_t)br0 * DDIM + n0 + bnc;
    size_t bs1 = (size_t)br1 * DDIM + n0 + bnc;

    const int NST = IDIM / 32;  // 64

#define DN_ISSUE(s_) do { \
        uint32_t st = sb + (uint32_t)(((s_) % STAGES) * DN_STAGE); \
        int k0 = (s_) * 32; \
        cpa16(st + dA0, a0 + k0, 16u); \
        cpa16(st + dA1, a1 + k0, 16u); \
        size_t o0 = bs0 + (size_t)k0 * DDIM, o1 = bs1 + (size_t)k0 * DDIM; \
        cpa16(st + DN_B + dB0, w + o0, 16u); \
        cpa16(st + DN_B + dB1, w + o1, 16u); \
    } while (0)

    DN_ISSUE(0); CP_COMMIT();
    DN_ISSUE(1); CP_COMMIT();
    DN_ISSUE(2); CP_COMMIT();

    int arow_l = (lane & 7) + ((lane >> 3) & 1) * 8;
    int akc_l = (lane >> 4) * 8;
    int mw = (wid >> 1) * 32;
    int nwo = (wid & 1) * 64;

    float acc[2][8][4];
#pragma unroll
    for (int i = 0; i < 2; i++)
#pragma unroll
        for (int j = 0; j < 8; j++)
#pragma unroll
            for (int q = 0; q < 4; q++) acc[i][j][q] = 0.f;

    for (int s = 0; s < NST; s++) {
        CP_WAIT(2);
        __syncthreads();
        if (s + 3 < NST) DN_ISSUE(s + 3);
        CP_COMMIT();
        uint32_t stg = sb + (uint32_t)((s % STAGES) * DN_STAGE);
#pragma unroll
        for (int ks = 0; ks < 32; ks += 16) {
            uint32_t aF[2][4];
#pragma unroll
            for (int mt = 0; mt < 2; mt++) {
                uint32_t ao = (mw + mt * 16 + arow_l) * A_STRIDE + (ks + akc_l) * 2;
                ldsm_x4(aF[mt], stg + DN_A + ao);
            }
#pragma unroll
            for (int g = 0; g < 4; g++) {
                uint32_t bo = (ks + arow_l) * DN_BSTRIDE + (nwo + g * 16 + akc_l) * 2;
                uint32_t bF[4];
                ldsm_x4_t(bF, stg + DN_B + bo);
#pragma unroll
                for (int mt = 0; mt < 2; mt++)
#pragma unroll
                    for (int sub = 0; sub < 2; sub++)
                        mma16816(acc[mt][g * 2 + sub], aF[mt], bF + sub * 2);
            }
        }
    }
    CP_WAIT(0);
    __syncthreads();

    // stage C (128x128 fp32) in smem, then red.add into zeroed out
    float* Cs = (float*)smem;
    int fr = lane >> 2, fc = (lane & 3) * 2;
#pragma unroll
    for (int mt = 0; mt < 2; mt++)
#pragma unroll
        for (int j = 0; j < 8; j++) {
            float* c = acc[mt][j];
            int r = mw + mt * 16 + fr, cl = nwo + j * 8 + fc;
            *(float2*)&Cs[r * 128 + cl] = make_float2(c[0], c[1]);
            *(float2*)&Cs[(r + 8) * 128 + cl] = make_float2(c[2], c[3]);
        }
    __syncthreads();

    int r = tid >> 1, cb = (tid & 1) * 64;
    int tokr = routed ? g_pair_token[m0 + r] : (m0 + r);
    if (tokr >= 0) {
        float wgt = routed ? g_pair_w[m0 + r] : 1.f;
        float* dst = out + (size_t)tokr * DDIM + n0 + cb;
        const float* src = &Cs[r * 128 + cb];
#pragma unroll
        for (int j = 0; j < 16; j++)
            red_add_v4(dst + j * 4, wgt * src[j * 4 + 0], wgt * src[j * 4 + 1],
                       wgt * src[j * 4 + 2], wgt * src[j * 4 + 3]);
    }
#undef DN_ISSUE
}

// ---------------- launch ----------------
extern "C" void kernel_launch(void* const* d_in, const int* in_sizes, int n_in,
                              void* d_out, int out_size) {
    const float* x       = (const float*)d_in[0];
    const float* Wg      = (const float*)d_in[1];
    const float* W_gate  = (const float*)d_in[2];
    const float* W_up    = (const float*)d_in[3];
    const float* W_down  = (const float*)d_in[4];
    const float* Ws_gate = (const float*)d_in[5];
    const float* Ws_up   = (const float*)d_in[6];
    const float* Ws_down = (const float*)d_in[7];
    float* out = (float*)d_out;

    cudaFuncSetAttribute(upgate_all, cudaFuncAttributeMaxDynamicSharedMemorySize, UG_SMEM);
    cudaFuncSetAttribute(down_all,   cudaFuncAttributeMaxDynamicSharedMemorySize, DN_SMEM);

    cudaMemsetAsync(out, 0, (size_t)out_size * sizeof(float));

    prep_kernel<<<NB_PREP, 256>>>(x, Wg, W_gate, Ws_gate, W_up, Ws_up, W_down, Ws_down);
    offsets_kernel<<<1, 256>>>(out, out_size);
    scatter_kernel<<<(NTOK + 255) / 256, 256>>>();

    upgate_all<<<dim3(IDIM / 64, NSHARED_TILES + NTILES), 256, UG_SMEM>>>();
    down_all<<<dim3(DDIM / 128, NSHARED_TILES + NTILES), 256, DN_SMEM>>>(out);
}